// round 1
// baseline (speedup 1.0000x reference)
#include <cuda_runtime.h>
#include <math.h>

// Problem constants (fixed shapes per reference)
#define BB 8
#define NN 32768
#define CC 4
#define MM 11          // memory length (taps)
#define DD 5           // degree
#define HALO (MM - 1)  // 10

#define TILE 256
#define THREADS 256
#define SAMP ((TILE + HALO) * CC)   // complex samples staged per block = 1064
#define NTILES (NN / TILE)          // 128

__global__ __launch_bounds__(THREADS)
void gmp_fir_kernel(const float* __restrict__ x,
                    const float* __restrict__ W,
                    float* __restrict__ out)
{
    __shared__ float s_re[SAMP], s_im[SAMP];
    __shared__ float s_a1[SAMP], s_a2[SAMP], s_a3[SAMP], s_a4[SAMP];
    __shared__ float s_W[CC * DD * MM];   // 220 floats

    const int tile = blockIdx.x % NTILES;
    const int b    = blockIdx.x / NTILES;
    const int n0   = tile * TILE;

    // Stage the tiny weight matrix
    for (int i = threadIdx.x; i < CC * DD * MM; i += THREADS)
        s_W[i] = W[i];

    // Stage tile + causal halo; compute amplitude powers once per sample.
    // Sample slot i <-> (n = n0 - HALO + i/CC, c = i%CC). Contiguous float2 loads.
    const float2* x2 = (const float2*)x + (size_t)b * NN * CC;
    for (int i = threadIdx.x; i < SAMP; i += THREADS) {
        const int n = n0 - HALO + (i >> 2);   // i / CC
        const int c = i & (CC - 1);
        float re = 0.f, im = 0.f;
        if (n >= 0) {
            float2 v = x2[(size_t)n * CC + c];
            re = v.x; im = v.y;
        }
        const float a  = sqrtf(re * re + im * im);
        const float a2 = a * a;
        s_re[i] = re;      s_im[i] = im;
        s_a1[i] = a;       s_a2[i] = a2;
        s_a3[i] = a2 * a;  s_a4[i] = a2 * a2;
    }
    __syncthreads();

    // Each thread produces TILE*CC/THREADS = 4 outputs.
    float2* o2 = (float2*)out + ((size_t)b * NN + n0) * CC;
    #pragma unroll
    for (int k = 0; k < (TILE * CC) / THREADS; ++k) {
        const int o = threadIdx.x + k * THREADS;   // o = nl*CC + c
        const int c = o & (CC - 1);
        const float* wc = s_W + c * (DD * MM);
        float accr = 0.f, acci = 0.f;
        #pragma unroll
        for (int j = 0; j < MM; ++j) {
            const int idx = o + j * CC;            // (nl+j)*CC + c : stride-1 across warp
            float p = wc[j];
            p = fmaf(wc[     MM + j], s_a1[idx], p);
            p = fmaf(wc[2 *  MM + j], s_a2[idx], p);
            p = fmaf(wc[3 *  MM + j], s_a3[idx], p);
            p = fmaf(wc[4 *  MM + j], s_a4[idx], p);
            accr = fmaf(s_re[idx], p, accr);
            acci = fmaf(s_im[idx], p, acci);
        }
        o2[o] = make_float2(accr, acci);
    }
}

extern "C" void kernel_launch(void* const* d_in, const int* in_sizes, int n_in,
                              void* d_out, int out_size)
{
    const float* x = (const float*)d_in[0];   // [B,N,C,2] fp32
    const float* W = (const float*)d_in[1];   // [C, D*M]  fp32
    float* out = (float*)d_out;               // [B,N,C,2] fp32
    (void)in_sizes; (void)n_in; (void)out_size;

    dim3 grid(BB * NTILES);   // 1024 blocks
    gmp_fir_kernel<<<grid, THREADS>>>(x, W, out);
}

// round 2
// speedup vs baseline: 1.1356x; 1.1356x over previous
#include <cuda_runtime.h>
#include <math.h>

// Fixed problem shape
#define BB 8
#define NN 32768
#define CC 4
#define MM 11          // taps
#define DD 5           // degree
#define HALO (MM - 1)  // 10

#define TILE 256
#define THREADS 256
#define KPT ((TILE * CC) / THREADS)       // outputs per thread = 4
#define SAMP ((TILE + HALO) * CC)         // staged complex samples = 1064
#define NTILES (NN / TILE)                // 128

// out[b,c,n] = sum_{j=0..10} z[n-10+j] * P_{c,j}(|z[n-10+j]|)
// P_{c,j}(a) = W[c,j] + W[c,11+j] a + W[c,22+j] a^2 + W[c,33+j] a^3 + W[c,44+j] a^4

__global__ __launch_bounds__(THREADS)
void gmp_fir_kernel(const float* __restrict__ x,
                    const float* __restrict__ W,
                    float* __restrict__ out)
{
    __shared__ float4 s_d[SAMP];          // (re, im, a, a^2) per sample
    __shared__ float  s_W[CC * DD * MM];  // 220 floats

    const int tile = blockIdx.x % NTILES;
    const int b    = blockIdx.x / NTILES;
    const int n0   = tile * TILE;

    for (int i = threadIdx.x; i < CC * DD * MM; i += THREADS)
        s_W[i] = W[i];

    // Stage tile + causal halo. One float4 global load = 2 complex samples
    // (layout [n][c][re,im], CC=4 -> even sample index pairs share n).
    const float4* x4 = (const float4*)x + (size_t)b * NN * (CC / 2);
    #pragma unroll
    for (int p = threadIdx.x; p < SAMP / 2; p += THREADS) {
        const int i = 2 * p;                       // even sample slot
        const int n = n0 - HALO + (i >> 2);
        const int cp = (i >> 1) & 1;               // channel pair 0:{0,1} 1:{2,3}
        float4 v = make_float4(0.f, 0.f, 0.f, 0.f);
        if (n >= 0)
            v = x4[(size_t)n * 2 + cp];
        const float q0 = v.x * v.x + v.y * v.y;
        const float q1 = v.z * v.z + v.w * v.w;
        s_d[i]     = make_float4(v.x, v.y, sqrtf(q0), q0);
        s_d[i + 1] = make_float4(v.z, v.w, sqrtf(q1), q1);
    }
    __syncthreads();

    // Each thread: fixed channel c = tid & 3, outputs o = tid + k*256.
    const int c = threadIdx.x & (CC - 1);
    const float* wc = s_W + c * (DD * MM);

    float accr[KPT], acci[KPT];
    #pragma unroll
    for (int k = 0; k < KPT; ++k) { accr[k] = 0.f; acci[k] = 0.f; }

    #pragma unroll
    for (int j = 0; j < MM; ++j) {
        const float w0 = wc[j];
        const float w1 = wc[MM + j];
        const float w2 = wc[2 * MM + j];
        const float w3 = wc[3 * MM + j];
        const float w4 = wc[4 * MM + j];
        #pragma unroll
        for (int k = 0; k < KPT; ++k) {
            const int o = threadIdx.x + k * THREADS;
            const float4 v = s_d[o + j * CC];      // stride-1 LDS.128, conflict-free
            // p = (w0 + a w1) + a^2 (w2 + a w3 + a^2 w4)
            float t = fmaf(v.z, w1, w0);
            float u = fmaf(v.z, w3, w2);
            u = fmaf(v.w, w4, u);
            const float p = fmaf(v.w, u, t);
            accr[k] = fmaf(v.x, p, accr[k]);
            acci[k] = fmaf(v.y, p, acci[k]);
        }
    }

    float2* o2 = (float2*)out + ((size_t)b * NN + n0) * CC;
    #pragma unroll
    for (int k = 0; k < KPT; ++k) {
        const int o = threadIdx.x + k * THREADS;
        o2[o] = make_float2(accr[k], acci[k]);
    }
}

extern "C" void kernel_launch(void* const* d_in, const int* in_sizes, int n_in,
                              void* d_out, int out_size)
{
    const float* x = (const float*)d_in[0];   // [B,N,C,2] fp32
    const float* W = (const float*)d_in[1];   // [C, D*M]  fp32
    float* out = (float*)d_out;               // [B,N,C,2] fp32
    (void)in_sizes; (void)n_in; (void)out_size;

    gmp_fir_kernel<<<BB * NTILES, THREADS>>>(x, W, out);
}